// round 4
// baseline (speedup 1.0000x reference)
#include <cuda_runtime.h>

// QualityAwarePatchAugment — GB300 sm_103a — R4.
// Single fused kernel, one block per patch (4096 blocks x 256 threads).
// R4 changes vs R3: no per-thread register cache of the patch (re-read from
// smem in the apply phase) -> regs ~40 -> 6 blocks/SM instead of 4; per-patch
// scalars prefetched in parallel at kernel start.

__device__ __forceinline__ float clipf(float v) {
    return fminf(fmaxf(v, 0.0f), 1.0f);
}

__global__ void __launch_bounds__(256, 6) fused_kernel(
    const float4* __restrict__ img,
    const float4* __restrict__ noise,
    float4*       __restrict__ out,
    const float*  __restrict__ r_strong,
    const float*  __restrict__ r_drop,
    const float*  __restrict__ r_else,
    const float*  __restrict__ bright_f,
    const float*  __restrict__ contrast_f,
    const float*  __restrict__ slight_f,
    const int*    __restrict__ aug_choice,
    const int*    __restrict__ slight_choice)
{
    __shared__ float sm[32 * 256];          // [batch][row16][col16], 32 KB
    __shared__ float sh_s[32], sh_s2[32];
    __shared__ float s_scal[9];             // prefetched per-patch scalars
    __shared__ float4 s_meta;               // x=code bits, y=param, z=m_pp

    const int p  = blockIdx.x;              // patch index = ph*64 + pw
    const int ph = p >> 6;
    const int pw = p & 63;
    const int t  = threadIdx.x;
    const int b  = t >> 3;                  // batch 0..31
    const int l8 = t & 7;                   // 8 threads per batch

    // Prefetch decision scalars in parallel with the bulk img loads.
    if (t < 9) {
        const float* tabs[9] = {
            r_strong, r_drop, r_else, bright_f, contrast_f, slight_f,
            (const float*)aug_choice, (const float*)slight_choice, r_strong };
        s_scal[t] = tabs[t][p];             // ints stored as raw bits
    }

    // float4 base index of (batch b, patch row 0); img row stride = 256 f4
    const int f4base = (b << 18) + (ph << 12) + (pw << 2);
    float* const sm_b = sm + (b << 8);

    // ---- Phase 1: stream patch into smem, accumulate sum / sumsq ----------
    float s = 0.0f, s2 = 0.0f;
    #pragma unroll
    for (int k = 0; k < 8; k++) {
        const int fi  = l8 + (k << 3);      // float4 slot in patch, 0..63
        const int row = fi >> 2;
        const int c4  = fi & 3;
        const float4 v = img[f4base + (row << 8) + c4];
        s  += v.x + v.y + v.z + v.w;
        s2 += v.x * v.x + v.y * v.y + v.z * v.z + v.w * v.w;
        *reinterpret_cast<float4*>(sm_b + (row << 4) + (c4 << 2)) = v;
    }
    #pragma unroll
    for (int off = 4; off; off >>= 1) {
        s  += __shfl_down_sync(0xffffffffu, s,  off, 8);
        s2 += __shfl_down_sync(0xffffffffu, s2, off, 8);
    }
    if (l8 == 0) { sh_s[b] = s; sh_s2[b] = s2; }
    __syncthreads();

    // ---- Phase 2: warp 0 folds batches -> code / param / m_pp -------------
    if (t < 32) {
        const float bs  = sh_s[t];
        const float bs2 = sh_s2[t];
        const float mean = bs * (1.0f / 256.0f);
        float var = (bs2 - bs * bs * (1.0f / 256.0f)) * (1.0f / 255.0f); // ddof=1
        var = fmaxf(var, 0.0f);
        const float sd   = sqrtf(var);
        const float iq   = 1.0f - 2.0f * fabsf(mean - 0.5f);
        const float qual = (sd + iq + var) * (1.0f / 3.0f);

        float qs  = qual;
        float tot = bs;
        #pragma unroll
        for (int off = 16; off; off >>= 1) {
            qs  += __shfl_down_sync(0xffffffffu, qs,  off);
            tot += __shfl_down_sync(0xffffffffu, tot, off);
        }
        if (t == 0) {
            const float q   = qs  * (1.0f / 32.0f);
            const float mpp = tot * (1.0f / 8192.0f);   // 32 batches * 256 px

            const bool low    = q < 0.7f;
            const bool strong = low && (s_scal[0] < 0.8f);
            const bool drop   = low && (q < 0.3f) && (s_scal[1] < 0.1f);
            const bool els    = (!low) && (s_scal[2] < 0.3f);

            int code = 0;
            if (strong) code = __float_as_int(s_scal[6]) + 1;   // aug_choice+1
            if (els)    code = __float_as_int(s_scal[7]) + 5;   // slight+5
            if (drop)   code = 7;

            float param = 0.0f;
            switch (code) {
                case 1: param = 0.1f;       break;
                case 3: param = s_scal[3];  break;   // bright_f
                case 4: param = s_scal[4];  break;   // contrast_f
                case 5: param = 0.05f;      break;
                case 6: param = s_scal[5];  break;   // slight_f
                default: break;
            }
            s_meta = make_float4(__int_as_float(code), param, mpp, 0.0f);
        }
    }
    __syncthreads();

    const int   code  = __float_as_int(s_meta.x);
    const float param = s_meta.y;
    const float mpp   = s_meta.z;

    // ---- Phase 3: apply (block-uniform branch; patch read back from smem) -
    if (code == 0) {                              // identity (~20%)
        #pragma unroll
        for (int k = 0; k < 8; k++) {
            const int fi  = l8 + (k << 3);
            const int row = fi >> 2, c4 = fi & 3;
            const float4 v = *reinterpret_cast<const float4*>(
                sm_b + (row << 4) + (c4 << 2));
            out[f4base + (row << 8) + c4] = v;
        }
    } else if (code == 1 || code == 5) {          // noise / slight noise
        #pragma unroll
        for (int k = 0; k < 8; k++) {
            const int fi  = l8 + (k << 3);
            const int row = fi >> 2, c4 = fi & 3;
            const int gi  = f4base + (row << 8) + c4;
            const float4 v = *reinterpret_cast<const float4*>(
                sm_b + (row << 4) + (c4 << 2));
            const float4 n = __ldcs(&noise[gi]);
            float4 o;
            o.x = clipf(fmaf(param, n.x, v.x));
            o.y = clipf(fmaf(param, n.y, v.y));
            o.z = clipf(fmaf(param, n.z, v.z));
            o.w = clipf(fmaf(param, n.w, v.w));
            out[gi] = o;
        }
    } else if (code == 2) {                       // 3x3 avg blur, zero-padded
        const float inv9 = 1.0f / 9.0f;
        #pragma unroll
        for (int k = 0; k < 8; k++) {
            const int fi  = l8 + (k << 3);
            const int row = fi >> 2;
            const int c0  = (fi & 3) << 2;        // first col of this float4
            float a0 = 0.f, a1 = 0.f, a2 = 0.f, a3 = 0.f;
            #pragma unroll
            for (int dr = -1; dr <= 1; dr++) {
                const int r = row + dr;
                if (r < 0 || r > 15) continue;
                const float* rp = sm_b + (r << 4);
                const float lft = (c0 > 0)  ? rp[c0 - 1] : 0.0f;
                const float rgt = (c0 < 12) ? rp[c0 + 4] : 0.0f;
                const float m0 = rp[c0], m1 = rp[c0 + 1];
                const float m2 = rp[c0 + 2], m3 = rp[c0 + 3];
                a0 += lft + m0 + m1;
                a1 += m0 + m1 + m2;
                a2 += m1 + m2 + m3;
                a3 += m2 + m3 + rgt;
            }
            float4 o = make_float4(a0 * inv9, a1 * inv9, a2 * inv9, a3 * inv9);
            out[f4base + (row << 8) + (fi & 3)] = o;
        }
    } else if (code == 3 || code == 6) {          // brightness variants
        #pragma unroll
        for (int k = 0; k < 8; k++) {
            const int fi  = l8 + (k << 3);
            const int row = fi >> 2, c4 = fi & 3;
            const float4 v = *reinterpret_cast<const float4*>(
                sm_b + (row << 4) + (c4 << 2));
            float4 o;
            o.x = clipf(v.x * param);
            o.y = clipf(v.y * param);
            o.z = clipf(v.z * param);
            o.w = clipf(v.w * param);
            out[f4base + (row << 8) + c4] = o;
        }
    } else if (code == 4) {                       // contrast about m_pp
        #pragma unroll
        for (int k = 0; k < 8; k++) {
            const int fi  = l8 + (k << 3);
            const int row = fi >> 2, c4 = fi & 3;
            const float4 v = *reinterpret_cast<const float4*>(
                sm_b + (row << 4) + (c4 << 2));
            float4 o;
            o.x = clipf(fmaf(v.x - mpp, param, mpp));
            o.y = clipf(fmaf(v.y - mpp, param, mpp));
            o.z = clipf(fmaf(v.z - mpp, param, mpp));
            o.w = clipf(fmaf(v.w - mpp, param, mpp));
            out[f4base + (row << 8) + c4] = o;
        }
    } else {                                      // 7: drop -> zeros
        const float4 z = make_float4(0.f, 0.f, 0.f, 0.f);
        #pragma unroll
        for (int k = 0; k < 8; k++) {
            const int fi = l8 + (k << 3);
            out[f4base + ((fi >> 2) << 8) + (fi & 3)] = z;
        }
    }
}

extern "C" void kernel_launch(void* const* d_in, const int* in_sizes, int n_in,
                              void* d_out, int out_size)
{
    fused_kernel<<<4096, 256>>>(
        (const float4*)d_in[0],   // img
        (const float4*)d_in[1],   // noise
        (float4*)d_out,
        (const float*)d_in[2],    // r_strong
        (const float*)d_in[3],    // r_drop
        (const float*)d_in[4],    // r_else
        (const float*)d_in[5],    // bright_f
        (const float*)d_in[6],    // contrast_f
        (const float*)d_in[7],    // slight_f
        (const int*)d_in[8],      // aug_choice
        (const int*)d_in[9]);     // slight_choice
}

// round 5
// speedup vs baseline: 1.2742x; 1.2742x over previous
#include <cuda_runtime.h>
#include <cstdint>

// QualityAwarePatchAugment — GB300 sm_103a — R5.
// One fused kernel, one block per patch (4096 x 256). Lessons applied:
//   R3: fusing removes the 2nd img read (traffic 410->272 MB).
//   R4: forcing low regs killed LDG MLP (8 in-flight LDG.128 need 32 regs).
//   R5: cp.async (LDGSTS) img->smem needs NO landing registers -> deep MLP at
//       ~40 regs -> 6 blocks/SM. Single __syncthreads per block: stats read
//       only own-thread slots (wait_group 0 suffices), and the batch-fold is
//       done redundantly per-warp (no warp0 serial section, no 2nd barrier).

__device__ __forceinline__ float clipf(float v) {
    return fminf(fmaxf(v, 0.0f), 1.0f);
}

__device__ __forceinline__ void cp16(uint32_t smem_dst, const void* gptr) {
    asm volatile("cp.async.cg.shared.global [%0], [%1], 16;"
                 :: "r"(smem_dst), "l"(gptr));
}

__global__ void __launch_bounds__(256, 6) fused_kernel(
    const float4* __restrict__ img,
    const float4* __restrict__ noise,
    float4*       __restrict__ out,
    const float*  __restrict__ r_strong,
    const float*  __restrict__ r_drop,
    const float*  __restrict__ r_else,
    const float*  __restrict__ bright_f,
    const float*  __restrict__ contrast_f,
    const float*  __restrict__ slight_f,
    const int*    __restrict__ aug_choice,
    const int*    __restrict__ slight_choice)
{
    __shared__ float sm[32 * 256];          // [batch][row16][col16], 32 KB
    __shared__ float sh_s[32], sh_s2[32];
    __shared__ float s_scal[8];             // per-patch decision scalars

    const int p    = blockIdx.x;            // patch index = ph*64 + pw
    const int ph   = p >> 6;
    const int pw   = p & 63;
    const int t    = threadIdx.x;
    const int b    = t >> 3;                // batch 0..31
    const int l8   = t & 7;                 // 8 threads per batch
    const int lane = t & 31;

    // Prefetch the 8 decision scalars (plain loads; done before the barrier).
    switch (t) {
        case 0: s_scal[0] = r_strong[p];                        break;
        case 1: s_scal[1] = r_drop[p];                          break;
        case 2: s_scal[2] = r_else[p];                          break;
        case 3: s_scal[3] = bright_f[p];                        break;
        case 4: s_scal[4] = contrast_f[p];                      break;
        case 5: s_scal[5] = slight_f[p];                        break;
        case 6: s_scal[6] = __int_as_float(aug_choice[p]);      break;
        case 7: s_scal[7] = __int_as_float(slight_choice[p]);   break;
        default: break;
    }

    // float4 base of (batch b, patch row 0); img row stride = 256 float4
    const int f4base = (b << 18) + (ph << 12) + (pw << 2);
    float* const sm_b = sm + (b << 8);
    const uint32_t sm_b_u = (uint32_t)__cvta_generic_to_shared(sm_b);

    // ---- Phase 0: async-copy the patch into smem (no landing registers) ---
    #pragma unroll
    for (int k = 0; k < 8; k++) {
        const int fi  = l8 + (k << 3);      // float4 slot 0..63
        const int row = fi >> 2;
        const int c4  = fi & 3;
        cp16(sm_b_u + (((row << 4) + (c4 << 2)) << 2),
             img + f4base + (row << 8) + c4);
    }
    asm volatile("cp.async.commit_group;");
    asm volatile("cp.async.wait_group 0;" ::: "memory");

    // ---- Phase 1: per-thread stats from own smem slots ---------------------
    float s = 0.0f, s2 = 0.0f;
    #pragma unroll
    for (int k = 0; k < 8; k++) {
        const int fi = l8 + (k << 3);
        const float4 v = *reinterpret_cast<const float4*>(
            sm_b + ((fi >> 2) << 4) + ((fi & 3) << 2));
        s  += v.x + v.y + v.z + v.w;
        s2 += v.x * v.x + v.y * v.y + v.z * v.z + v.w * v.w;
    }
    #pragma unroll
    for (int off = 4; off; off >>= 1) {
        s  += __shfl_down_sync(0xffffffffu, s,  off, 8);
        s2 += __shfl_down_sync(0xffffffffu, s2, off, 8);
    }
    if (l8 == 0) { sh_s[b] = s; sh_s2[b] = s2; }
    __syncthreads();                        // the ONLY block-wide barrier

    // ---- Phase 2: redundant per-warp batch fold (all lanes get result) ----
    float q, mpp;
    {
        const float bs  = sh_s[lane];       // lane i <- batch i (broadcast-free)
        const float bs2 = sh_s2[lane];
        const float mean = bs * (1.0f / 256.0f);
        float var = (bs2 - bs * bs * (1.0f / 256.0f)) * (1.0f / 255.0f); // ddof=1
        var = fmaxf(var, 0.0f);
        const float sd   = sqrtf(var);
        const float iq   = 1.0f - 2.0f * fabsf(mean - 0.5f);
        float qs  = (sd + iq + var) * (1.0f / 3.0f);
        float tot = bs;
        #pragma unroll
        for (int off = 16; off; off >>= 1) {    // xor butterfly: all lanes
            qs  += __shfl_xor_sync(0xffffffffu, qs,  off);
            tot += __shfl_xor_sync(0xffffffffu, tot, off);
        }
        q   = qs  * (1.0f / 32.0f);
        mpp = tot * (1.0f / 8192.0f);           // 32 batches * 256 px
    }

    const bool low    = q < 0.7f;
    const bool strong = low && (s_scal[0] < 0.8f);
    const bool drop   = low && (q < 0.3f) && (s_scal[1] < 0.1f);
    const bool els    = (!low) && (s_scal[2] < 0.3f);

    int code = 0;
    if (strong) code = __float_as_int(s_scal[6]) + 1;   // aug_choice + 1
    if (els)    code = __float_as_int(s_scal[7]) + 5;   // slight_choice + 5
    if (drop)   code = 7;

    float param = 0.0f;
    switch (code) {
        case 1: param = 0.1f;       break;
        case 3: param = s_scal[3];  break;   // bright_f
        case 4: param = s_scal[4];  break;   // contrast_f
        case 5: param = 0.05f;      break;
        case 6: param = s_scal[5];  break;   // slight_f
        default: break;
    }

    // ---- Phase 3: apply (block-uniform branch; patch read from smem) ------
    if (code == 0) {                              // identity (~20%)
        #pragma unroll
        for (int k = 0; k < 8; k++) {
            const int fi  = l8 + (k << 3);
            const int row = fi >> 2, c4 = fi & 3;
            const float4 v = *reinterpret_cast<const float4*>(
                sm_b + (row << 4) + (c4 << 2));
            out[f4base + (row << 8) + c4] = v;
        }
    } else if (code == 1 || code == 5) {          // noise / slight noise
        #pragma unroll
        for (int k = 0; k < 8; k++) {
            const int fi  = l8 + (k << 3);
            const int row = fi >> 2, c4 = fi & 3;
            const int gi  = f4base + (row << 8) + c4;
            const float4 v = *reinterpret_cast<const float4*>(
                sm_b + (row << 4) + (c4 << 2));
            const float4 n = __ldcs(&noise[gi]);
            float4 o;
            o.x = clipf(fmaf(param, n.x, v.x));
            o.y = clipf(fmaf(param, n.y, v.y));
            o.z = clipf(fmaf(param, n.z, v.z));
            o.w = clipf(fmaf(param, n.w, v.w));
            out[gi] = o;
        }
    } else if (code == 2) {                       // 3x3 avg blur, zero-padded
        const float inv9 = 1.0f / 9.0f;
        #pragma unroll
        for (int k = 0; k < 8; k++) {
            const int fi  = l8 + (k << 3);
            const int row = fi >> 2;
            const int c0  = (fi & 3) << 2;        // first col of this float4
            float a0 = 0.f, a1 = 0.f, a2 = 0.f, a3 = 0.f;
            #pragma unroll
            for (int dr = -1; dr <= 1; dr++) {
                const int r = row + dr;
                if (r < 0 || r > 15) continue;
                const float* rp = sm_b + (r << 4);
                const float lft = (c0 > 0)  ? rp[c0 - 1] : 0.0f;
                const float rgt = (c0 < 12) ? rp[c0 + 4] : 0.0f;
                const float m0 = rp[c0], m1 = rp[c0 + 1];
                const float m2 = rp[c0 + 2], m3 = rp[c0 + 3];
                a0 += lft + m0 + m1;
                a1 += m0 + m1 + m2;
                a2 += m1 + m2 + m3;
                a3 += m2 + m3 + rgt;
            }
            float4 o = make_float4(a0 * inv9, a1 * inv9, a2 * inv9, a3 * inv9);
            out[f4base + (row << 8) + (fi & 3)] = o;
        }
    } else if (code == 3 || code == 6) {          // brightness variants
        #pragma unroll
        for (int k = 0; k < 8; k++) {
            const int fi  = l8 + (k << 3);
            const int row = fi >> 2, c4 = fi & 3;
            const float4 v = *reinterpret_cast<const float4*>(
                sm_b + (row << 4) + (c4 << 2));
            float4 o;
            o.x = clipf(v.x * param);
            o.y = clipf(v.y * param);
            o.z = clipf(v.z * param);
            o.w = clipf(v.w * param);
            out[f4base + (row << 8) + c4] = o;
        }
    } else if (code == 4) {                       // contrast about m_pp
        #pragma unroll
        for (int k = 0; k < 8; k++) {
            const int fi  = l8 + (k << 3);
            const int row = fi >> 2, c4 = fi & 3;
            const float4 v = *reinterpret_cast<const float4*>(
                sm_b + (row << 4) + (c4 << 2));
            float4 o;
            o.x = clipf(fmaf(v.x - mpp, param, mpp));
            o.y = clipf(fmaf(v.y - mpp, param, mpp));
            o.z = clipf(fmaf(v.z - mpp, param, mpp));
            o.w = clipf(fmaf(v.w - mpp, param, mpp));
            out[f4base + (row << 8) + c4] = o;
        }
    } else {                                      // 7: drop -> zeros
        const float4 z = make_float4(0.f, 0.f, 0.f, 0.f);
        #pragma unroll
        for (int k = 0; k < 8; k++) {
            const int fi = l8 + (k << 3);
            out[f4base + ((fi >> 2) << 8) + (fi & 3)] = z;
        }
    }
}

extern "C" void kernel_launch(void* const* d_in, const int* in_sizes, int n_in,
                              void* d_out, int out_size)
{
    fused_kernel<<<4096, 256>>>(
        (const float4*)d_in[0],   // img
        (const float4*)d_in[1],   // noise
        (float4*)d_out,
        (const float*)d_in[2],    // r_strong
        (const float*)d_in[3],    // r_drop
        (const float*)d_in[4],    // r_else
        (const float*)d_in[5],    // bright_f
        (const float*)d_in[6],    // contrast_f
        (const float*)d_in[7],    // slight_f
        (const int*)d_in[8],      // aug_choice
        (const int*)d_in[9]);     // slight_choice
}